// round 5
// baseline (speedup 1.0000x reference)
#include <cuda_runtime.h>

#define NMAX 100000
#define EMAX 1600000
#define GMAX 128

// ---------------- device scratch (zero-init at load; kernels restore zeros after use) ----
__device__ float4 g_h4[2][NMAX * 8];     // h double buffers (float4 rows)
__device__ float  g_as[2][NMAX];
__device__ float  g_ad[2][NMAX];
__device__ float  g_vacc[NMAX];          // running readout scalar per node
__device__ int    g_deg[NMAX];           // must be 0 on entry to k_countB
__device__ int    g_rp[NMAX + 1];
__device__ int    g_cur[NMAX];
__device__ float4 g_pack[EMAX];          // {src_bits, cae0, cae1, cae2} CSR order
__device__ float  g_easum[3];            // must be 0 on entry to k_countB
// g_prm: [0..288) Weff(9x32), [288..320) beff, [320+5l..): u0,u1,u2,c,aloop
__device__ float  g_prm[352];
__device__ float  g_gsum[GMAX];          // must be 0 on entry to k_aggL
__device__ float  g_gcnt[GMAX];

__device__ __forceinline__ float lrelu(float x) { return x > 0.f ? x : 0.2f * x; }
__device__ __forceinline__ float wreduce(float v) {
#pragma unroll
    for (int o = 16; o; o >>= 1) v += __shfl_xor_sync(0xffffffffu, v, o);
    return v;
}

// ---------------- 1: degree count + edge_attr column sums ----------------
__global__ void k_countB(const int* __restrict__ dst, const float* __restrict__ ea, int E) {
    __shared__ float sh[3];
    if (threadIdx.x < 3) sh[threadIdx.x] = 0.f;
    __syncthreads();
    float s0 = 0.f, s1 = 0.f, s2 = 0.f;
    for (int e = blockIdx.x * blockDim.x + threadIdx.x; e < E; e += gridDim.x * blockDim.x) {
        atomicAdd(&g_deg[dst[e]], 1);
        s0 += ea[3 * e]; s1 += ea[3 * e + 1]; s2 += ea[3 * e + 2];
    }
    s0 = wreduce(s0); s1 = wreduce(s1); s2 = wreduce(s2);
    if ((threadIdx.x & 31) == 0) {
        atomicAdd(&sh[0], s0); atomicAdd(&sh[1], s1); atomicAdd(&sh[2], s2);
    }
    __syncthreads();
    if (threadIdx.x < 3) atomicAdd(&g_easum[threadIdx.x], sh[threadIdx.x]);
}

// ---------------- 2: folded params + CSR scan + self-cleanup ----------------
__global__ void k_scanprep(const float* __restrict__ W_ne, const float* __restrict__ b_ne,
                           const float* __restrict__ W_ee, const float* __restrict__ b_ee,
                           const float* __restrict__ W0,
                           const float* __restrict__ We0, const float* __restrict__ ae0,
                           const float* __restrict__ We1, const float* __restrict__ ae1,
                           const float* __restrict__ We2, const float* __restrict__ ae2,
                           int n, int E) {
    int t = threadIdx.x;
    if (t < 288) {
        int r = t / 32, j = t % 32;
        float s = 0.f;
        for (int d = 0; d < 16; d++) s += W_ne[r * 16 + d] * W0[d * 32 + j];
        g_prm[t] = s;
    } else if (t < 320) {
        int j = t - 288;
        float s = 0.f;
        for (int d = 0; d < 16; d++) s += b_ne[d] * W0[d * 32 + j];
        g_prm[288 + j] = s;
    } else if (t < 416) {
        int l = (t - 320) >> 5, j = t & 31;
        const float* We = (l == 0) ? We0 : (l == 1) ? We1 : We2;
        const float* ae = (l == 0) ? ae0 : (l == 1) ? ae1 : ae2;
        float aej = ae[j];
        float v0 = wreduce(We[j] * aej);
        float v1 = wreduce(We[32 + j] * aej);
        if (j == 0) {
            float u0 = W_ee[0] * v0 + W_ee[1] * v1;
            float u1 = W_ee[2] * v0 + W_ee[3] * v1;
            float u2 = W_ee[4] * v0 + W_ee[5] * v1;
            float c  = b_ee[0] * v0 + b_ee[1] * v1;
            float inv = 1.f / (float)E;
            g_prm[320 + 5 * l + 0] = u0;
            g_prm[320 + 5 * l + 1] = u1;
            g_prm[320 + 5 * l + 2] = u2;
            g_prm[320 + 5 * l + 3] = c;
            g_prm[320 + 5 * l + 4] = g_easum[0] * inv * u0 + g_easum[1] * inv * u1
                                   + g_easum[2] * inv * u2 + c;
        }
    }
    __shared__ int ssum[1024];
    int per = (n + 1023) / 1024;
    int b0 = t * per, b1 = min(n, b0 + per);
    int s = 0;
    for (int i = b0; i < b1; i++) s += g_deg[i];
    ssum[t] = s;
    __syncthreads();
    for (int o = 1; o < 1024; o <<= 1) {
        int v = (t >= o) ? ssum[t - o] : 0;
        __syncthreads();
        ssum[t] += v;
        __syncthreads();
    }
    int run = t ? ssum[t - 1] : 0;
    for (int i = b0; i < b1; i++) {
        g_rp[i] = run; g_cur[i] = run;
        run += g_deg[i];
    }
    if (t == 1023) g_rp[n] = run;
    __syncthreads();
    // restore zeros for next invocation
    for (int i = b0; i < b1; i++) g_deg[i] = 0;
    if (t < 3) g_easum[t] = 0.f;
}

// ---------------- 3: CSR scatter (blocks < eb) + layer-0 node matmul (rest) ----------------
__global__ void __launch_bounds__(256) k_build(const int* __restrict__ src,
                                               const int* __restrict__ dst,
                                               const float* __restrict__ ea,
                                               const float* __restrict__ nf,
                                               const float* __restrict__ as0,
                                               const float* __restrict__ ad0,
                                               int E, int n, int eb) {
    if ((int)blockIdx.x < eb) {
        int e = blockIdx.x * 256 + threadIdx.x;
        if (e >= E) return;
        int d = dst[e];
        int pos = atomicAdd(&g_cur[d], 1);
        float e0 = ea[3 * e], e1 = ea[3 * e + 1], e2 = ea[3 * e + 2];
        const float* p = &g_prm[320];
        float4 r;
        r.x = __int_as_float(src[e]);
        r.y = e0 * p[0]  + e1 * p[1]  + e2 * p[2]  + p[3];
        r.z = e0 * p[5]  + e1 * p[6]  + e2 * p[7]  + p[8];
        r.w = e0 * p[10] + e1 * p[11] + e2 * p[12] + p[13];
        g_pack[pos] = r;
    } else {
        __shared__ float Ws[288], bs[32], av[64];
        int t = threadIdx.x;
        for (int k = t; k < 288; k += 256) Ws[k] = g_prm[k];
        if (t < 32) { bs[t] = g_prm[288 + t]; av[t] = as0[t]; av[32 + t] = ad0[t]; }
        __syncthreads();
        int i = ((int)blockIdx.x - eb) * 256 + t;
        if (i >= n) return;
        float x[9];
#pragma unroll
        for (int r = 0; r < 9; r++) x[r] = nf[i * 9 + r];
        float acc[32];
#pragma unroll
        for (int j = 0; j < 32; j++) acc[j] = bs[j];
#pragma unroll
        for (int r = 0; r < 9; r++)
#pragma unroll
            for (int j = 0; j < 32; j++) acc[j] += x[r] * Ws[r * 32 + j];
        float sa = 0.f, sd = 0.f;
#pragma unroll
        for (int j = 0; j < 32; j++) { sa += acc[j] * av[j]; sd += acc[j] * av[32 + j]; }
        g_as[0][i] = sa; g_ad[0][i] = sd;
        float4* o = &g_h4[0][i * 8];
#pragma unroll
        for (int q = 0; q < 8; q++)
            o[q] = make_float4(acc[4 * q], acc[4 * q + 1], acc[4 * q + 2], acc[4 * q + 3]);
    }
}

// ---------------- core gather: 8 edges in parallel across 4-lane groups ----------------
template <int L>
__device__ __forceinline__ float agg_node(int d, int j, const float4* __restrict__ hc,
                                          const float* __restrict__ asc, float adst_d,
                                          float aloop, float asrc_d, float* __restrict__ xrow) {
    int beg = g_rp[d], end = g_rp[d + 1];
    float4 accA = make_float4(0.f, 0.f, 0.f, 0.f);
    float4 accB = make_float4(0.f, 0.f, 0.f, 0.f);
    float denom = 0.f;
    int c4 = j & 3;      // float4 column pair (c4 and 4+c4)
    int grp = j >> 2;    // edge group 0..7
    for (int base = beg; base < end; base += 32) {
        int idx = base + j;
        int s = 0; float ex = 0.f;
        if (idx < end) {
            float4 r = g_pack[idx];
            s = __float_as_int(r.x);
            float ae = (L == 0) ? r.y : (L == 1) ? r.z : r.w;
            ex = __expf(lrelu(asc[s] + adst_d + ae));
        }
        denom += ex;
        int trips = (min(end - base, 32) + 7) >> 3;
#pragma unroll 2
        for (int k = 0; k < trips; k++) {
            int sl = k * 8 + grp;
            float exk = __shfl_sync(0xffffffffu, ex, sl);
            int   sk  = __shfl_sync(0xffffffffu, s, sl);
            float4 h0 = hc[sk * 8 + c4];
            float4 h1 = hc[sk * 8 + 4 + c4];
            accA.x += exk * h0.x; accA.y += exk * h0.y;
            accA.z += exk * h0.z; accA.w += exk * h0.w;
            accB.x += exk * h1.x; accB.y += exk * h1.y;
            accB.z += exk * h1.z; accB.w += exk * h1.w;
        }
    }
    // reduce the 8 edge-groups (lanes sharing j&3)
#pragma unroll
    for (int o = 4; o <= 16; o <<= 1) {
        accA.x += __shfl_xor_sync(0xffffffffu, accA.x, o);
        accA.y += __shfl_xor_sync(0xffffffffu, accA.y, o);
        accA.z += __shfl_xor_sync(0xffffffffu, accA.z, o);
        accA.w += __shfl_xor_sync(0xffffffffu, accA.w, o);
        accB.x += __shfl_xor_sync(0xffffffffu, accB.x, o);
        accB.y += __shfl_xor_sync(0xffffffffu, accB.y, o);
        accB.z += __shfl_xor_sync(0xffffffffu, accB.z, o);
        accB.w += __shfl_xor_sync(0xffffffffu, accB.w, o);
    }
    if (j < 4) {                       // lane j holds cols [4j..4j+3] and [16+4j..16+4j+3]
        ((float4*)xrow)[j] = accA;
        ((float4*)xrow)[4 + j] = accB;
    }
    __syncwarp();
    float a = xrow[j];
    denom = wreduce(denom);
    float le = __expf(lrelu(asrc_d + adst_d + aloop));
    float inv = 1.f / (denom + le + 1e-16f);
    float hdj = ((const float*)hc)[d * 32 + j];
    return (a + le * hdj) * inv;
}

// ---------------- 4,5: layer 0/1 agg + readout partial + next-layer node matmul ----------
template <int L>
__global__ void __launch_bounds__(256) k_aggF(const float* __restrict__ Wn,
                                              const float* __restrict__ bbc,
                                              const float* __restrict__ asn,
                                              const float* __restrict__ adn,
                                              const float* __restrict__ Wl3, int n) {
    const float4* hc = g_h4[L & 1];
    float4*       hn = g_h4[(L & 1) ^ 1];
    constexpr int P = L & 1;
    __shared__ float Wns[1024], avs[64], bbs[32], wl3s[32];
    __shared__ float xsh[8][36];
    int t = threadIdx.x, j = t & 31, w = t >> 5;
    for (int k = t; k < 1024; k += 256) Wns[k] = Wn[k];
    if (t < 32) { bbs[t] = bbc[t]; avs[t] = asn[t]; avs[32 + t] = adn[t]; wl3s[t] = Wl3[L * 32 + t]; }
    __syncthreads();
    int d = blockIdx.x * 8 + w;
    if (d >= n) return;
    float adst_d = g_ad[P][d];
    float asrc_d = g_as[P][d];
    float xl = agg_node<L>(d, j, hc, g_as[P], adst_d, g_prm[320 + 5 * L + 4], asrc_d, xsh[w]);
    float y = xl + bbs[j];
    // readout partial: v_L = sum_j y * Wl3[L*32+j]
    float v = wreduce(y * wl3s[j]);
    if (j == 0) {
        if (L == 0) g_vacc[d] = v;
        else        g_vacc[d] += v;
    }
    // next-layer transform via smem broadcast
    xsh[w][j] = y;
    __syncwarp();
    const float4* xv4 = (const float4*)xsh[w];
    float h = 0.f;
#pragma unroll
    for (int q = 0; q < 8; q++) {
        float4 xv = xv4[q];
        h += xv.x * Wns[(4 * q) * 32 + j]     + xv.y * Wns[(4 * q + 1) * 32 + j]
           + xv.z * Wns[(4 * q + 2) * 32 + j] + xv.w * Wns[(4 * q + 3) * 32 + j];
    }
    ((float*)hn)[d * 32 + j] = h;
    float sa = wreduce(h * avs[j]);
    float sd = wreduce(h * avs[32 + j]);
    if (j == 0) { g_as[P ^ 1][d] = sa; g_ad[P ^ 1][d] = sd; }
}

// ---------------- 6: layer 2 agg + final readout ----------------
__global__ void __launch_bounds__(256) k_aggL(const int* __restrict__ batch,
                                              const float* __restrict__ Wl3,
                                              const float* __restrict__ bb2, int n) {
    __shared__ float wl3s[32], bbs[32];
    __shared__ float xsh[8][36];
    int t = threadIdx.x, j = t & 31, w = t >> 5;
    if (t < 32) { wl3s[t] = Wl3[64 + t]; bbs[t] = bb2[t]; }
    __syncthreads();
    int d = blockIdx.x * 8 + w;
    if (d >= n) return;
    float adst_d = g_ad[0][d];
    float asrc_d = g_as[0][d];
    float x3 = agg_node<2>(d, j, g_h4[0], g_as[0], adst_d, g_prm[320 + 10 + 4], asrc_d, xsh[w]);
    float v = wreduce((x3 + bbs[j]) * wl3s[j]);
    if (j == 0) {
        int g = batch[d];
        atomicAdd(&g_gsum[g], g_vacc[d] + v);
        atomicAdd(&g_gcnt[g], 1.f);
    }
}

// ---------------- 7: final mean + bias, restore zeros ----------------
__global__ void k_final(float* __restrict__ out, const float* __restrict__ b_l3, int G) {
    int g = blockIdx.x * blockDim.x + threadIdx.x;
    if (g < G) {
        out[g] = g_gsum[g] / fmaxf(g_gcnt[g], 1.f) + b_l3[0];
        g_gsum[g] = 0.f;
        g_gcnt[g] = 0.f;
    }
}

// ---------------- launch ----------------
extern "C" void kernel_launch(void* const* d_in, const int* in_sizes, int n_in,
                              void* d_out, int out_size) {
    const float* nf    = (const float*)d_in[0];
    const int*   ei    = (const int*)d_in[1];
    const float* ea    = (const float*)d_in[2];
    const int*   batch = (const int*)d_in[3];
    const float* W_ne  = (const float*)d_in[4];
    const float* b_ne  = (const float*)d_in[5];
    const float* W_ee  = (const float*)d_in[6];
    const float* b_ee  = (const float*)d_in[7];
    const float* W_l3  = (const float*)d_in[8];
    const float* b_l3  = (const float*)d_in[9];
    const float* W[3]   = {(const float*)d_in[10], (const float*)d_in[16], (const float*)d_in[22]};
    const float* as_[3] = {(const float*)d_in[11], (const float*)d_in[17], (const float*)d_in[23]};
    const float* ad_[3] = {(const float*)d_in[12], (const float*)d_in[18], (const float*)d_in[24]};
    const float* We_[3] = {(const float*)d_in[13], (const float*)d_in[19], (const float*)d_in[25]};
    const float* ae_[3] = {(const float*)d_in[14], (const float*)d_in[20], (const float*)d_in[26]};
    const float* bb_[3] = {(const float*)d_in[15], (const float*)d_in[21], (const float*)d_in[27]};

    int n = in_sizes[3];
    int E = in_sizes[1] / 2;
    int G = out_size;
    const int* src = ei;
    const int* dst = ei + E;

    int eb  = (E + 255) / 256;
    int nb  = (n + 255) / 256;
    int nbw = (n + 7) / 8;

    k_countB<<<1184, 256>>>(dst, ea, E);
    k_scanprep<<<1, 1024>>>(W_ne, b_ne, W_ee, b_ee, W[0],
                            We_[0], ae_[0], We_[1], ae_[1], We_[2], ae_[2], n, E);
    k_build<<<eb + nb, 256>>>(src, dst, ea, nf, as_[0], ad_[0], E, n, eb);
    k_aggF<0><<<nbw, 256>>>(W[1], bb_[0], as_[1], ad_[1], W_l3, n);
    k_aggF<1><<<nbw, 256>>>(W[2], bb_[1], as_[2], ad_[2], W_l3, n);
    k_aggL<<<nbw, 256>>>(batch, W_l3, bb_[2], n);
    k_final<<<1, 128>>>((float*)d_out, b_l3, G);
}

// round 6
// speedup vs baseline: 1.1844x; 1.1844x over previous
#include <cuda_runtime.h>

#define NMAX 100000
#define EMAX 1600000
#define GMAX 128
#define NPW 8   // nodes per warp in agg kernels

// ---------------- device scratch (zero-init at load; kernels restore zeros) ----------
__device__ float4 g_h4[2][NMAX * 8];     // h double buffers (float4 rows, 128B aligned)
__device__ float  g_as[2][NMAX];
__device__ float  g_ad[2][NMAX];
__device__ float  g_vacc[NMAX];          // running readout scalar per node
__device__ int    g_deg[NMAX];           // must be 0 on entry to k_countB
__device__ int    g_rp[NMAX + 1];
__device__ int    g_rank[EMAX];          // rank of edge within its dst bucket
__device__ float4 g_pack[EMAX];          // {src_bits, cae0, cae1, cae2} CSR order
__device__ float  g_easum[3];            // must be 0 on entry to k_countB
// g_prm: [0..288) Weff(9x32), [288..320) beff, [320+5l..): u0,u1,u2,c,aloop
__device__ float  g_prm[352];
__device__ float  g_gsum[GMAX];          // must be 0 on entry to k_aggL
__device__ float  g_gcnt[GMAX];

__device__ __forceinline__ float lrelu(float x) { return x > 0.f ? x : 0.2f * x; }
__device__ __forceinline__ float wreduce(float v) {
#pragma unroll
    for (int o = 16; o; o >>= 1) v += __shfl_xor_sync(0xffffffffu, v, o);
    return v;
}

// ---------------- 1: degree count (rank recorded) + edge_attr column sums ----------------
__global__ void k_countB(const int* __restrict__ dst, const float* __restrict__ ea, int E) {
    __shared__ float sh[3];
    if (threadIdx.x < 3) sh[threadIdx.x] = 0.f;
    __syncthreads();
    float s0 = 0.f, s1 = 0.f, s2 = 0.f;
    for (int e = blockIdx.x * blockDim.x + threadIdx.x; e < E; e += gridDim.x * blockDim.x) {
        g_rank[e] = atomicAdd(&g_deg[dst[e]], 1);
        s0 += ea[3 * e]; s1 += ea[3 * e + 1]; s2 += ea[3 * e + 2];
    }
    s0 = wreduce(s0); s1 = wreduce(s1); s2 = wreduce(s2);
    if ((threadIdx.x & 31) == 0) {
        atomicAdd(&sh[0], s0); atomicAdd(&sh[1], s1); atomicAdd(&sh[2], s2);
    }
    __syncthreads();
    if (threadIdx.x < 3) atomicAdd(&g_easum[threadIdx.x], sh[threadIdx.x]);
}

// ---------------- 2: folded params + CSR scan + self-cleanup ----------------
__global__ void k_scanprep(const float* __restrict__ W_ne, const float* __restrict__ b_ne,
                           const float* __restrict__ W_ee, const float* __restrict__ b_ee,
                           const float* __restrict__ W0,
                           const float* __restrict__ We0, const float* __restrict__ ae0,
                           const float* __restrict__ We1, const float* __restrict__ ae1,
                           const float* __restrict__ We2, const float* __restrict__ ae2,
                           int n, int E) {
    int t = threadIdx.x;
    if (t < 288) {
        int r = t / 32, j = t % 32;
        float s = 0.f;
        for (int d = 0; d < 16; d++) s += W_ne[r * 16 + d] * W0[d * 32 + j];
        g_prm[t] = s;
    } else if (t < 320) {
        int j = t - 288;
        float s = 0.f;
        for (int d = 0; d < 16; d++) s += b_ne[d] * W0[d * 32 + j];
        g_prm[288 + j] = s;
    } else if (t < 416) {
        int l = (t - 320) >> 5, j = t & 31;
        const float* We = (l == 0) ? We0 : (l == 1) ? We1 : We2;
        const float* ae = (l == 0) ? ae0 : (l == 1) ? ae1 : ae2;
        float aej = ae[j];
        float v0 = wreduce(We[j] * aej);
        float v1 = wreduce(We[32 + j] * aej);
        if (j == 0) {
            float u0 = W_ee[0] * v0 + W_ee[1] * v1;
            float u1 = W_ee[2] * v0 + W_ee[3] * v1;
            float u2 = W_ee[4] * v0 + W_ee[5] * v1;
            float c  = b_ee[0] * v0 + b_ee[1] * v1;
            float inv = 1.f / (float)E;
            g_prm[320 + 5 * l + 0] = u0;
            g_prm[320 + 5 * l + 1] = u1;
            g_prm[320 + 5 * l + 2] = u2;
            g_prm[320 + 5 * l + 3] = c;
            g_prm[320 + 5 * l + 4] = g_easum[0] * inv * u0 + g_easum[1] * inv * u1
                                   + g_easum[2] * inv * u2 + c;
        }
    }
    __shared__ int ssum[1024];
    int per = (n + 1023) / 1024;
    int b0 = t * per, b1 = min(n, b0 + per);
    int s = 0;
    for (int i = b0; i < b1; i++) s += g_deg[i];
    ssum[t] = s;
    __syncthreads();
    for (int o = 1; o < 1024; o <<= 1) {
        int v = (t >= o) ? ssum[t - o] : 0;
        __syncthreads();
        ssum[t] += v;
        __syncthreads();
    }
    int run = t ? ssum[t - 1] : 0;
    for (int i = b0; i < b1; i++) {
        g_rp[i] = run;
        run += g_deg[i];
    }
    if (t == 1023) g_rp[n] = run;
    __syncthreads();
    for (int i = b0; i < b1; i++) g_deg[i] = 0;   // restore zeros
    if (t < 3) g_easum[t] = 0.f;
}

// ---------------- 3: CSR scatter (no atomics) + layer-0 node matmul ----------------
__global__ void __launch_bounds__(256) k_build(const int* __restrict__ src,
                                               const int* __restrict__ dst,
                                               const float* __restrict__ ea,
                                               const float* __restrict__ nf,
                                               const float* __restrict__ as0,
                                               const float* __restrict__ ad0,
                                               int E, int n, int eb) {
    if ((int)blockIdx.x < eb) {
        int e = blockIdx.x * 256 + threadIdx.x;
        if (e >= E) return;
        int d = dst[e];
        int pos = g_rp[d] + g_rank[e];
        float e0 = ea[3 * e], e1 = ea[3 * e + 1], e2 = ea[3 * e + 2];
        const float* p = &g_prm[320];
        float4 r;
        r.x = __int_as_float(src[e]);
        r.y = e0 * p[0]  + e1 * p[1]  + e2 * p[2]  + p[3];
        r.z = e0 * p[5]  + e1 * p[6]  + e2 * p[7]  + p[8];
        r.w = e0 * p[10] + e1 * p[11] + e2 * p[12] + p[13];
        g_pack[pos] = r;
    } else {
        __shared__ float Ws[288], bs[32], av[64];
        int t = threadIdx.x;
        for (int k = t; k < 288; k += 256) Ws[k] = g_prm[k];
        if (t < 32) { bs[t] = g_prm[288 + t]; av[t] = as0[t]; av[32 + t] = ad0[t]; }
        __syncthreads();
        int i = ((int)blockIdx.x - eb) * 256 + t;
        if (i >= n) return;
        float x[9];
#pragma unroll
        for (int r = 0; r < 9; r++) x[r] = nf[i * 9 + r];
        float acc[32];
#pragma unroll
        for (int j = 0; j < 32; j++) acc[j] = bs[j];
#pragma unroll
        for (int r = 0; r < 9; r++)
#pragma unroll
            for (int j = 0; j < 32; j++) acc[j] += x[r] * Ws[r * 32 + j];
        float sa = 0.f, sd = 0.f;
#pragma unroll
        for (int j = 0; j < 32; j++) { sa += acc[j] * av[j]; sd += acc[j] * av[32 + j]; }
        g_as[0][i] = sa; g_ad[0][i] = sd;
        float4* o = &g_h4[0][i * 8];
#pragma unroll
        for (int q = 0; q < 8; q++)
            o[q] = make_float4(acc[4 * q], acc[4 * q + 1], acc[4 * q + 2], acc[4 * q + 3]);
    }
}

// ---------------- core gather: 4 edges in parallel, 1 LDG.128 per row ----------------
template <int L>
__device__ __forceinline__ float agg_node(int d, int j, const float4* __restrict__ hc,
                                          const float* __restrict__ asc, float adst_d,
                                          float aloop, float asrc_d) {
    int beg = g_rp[d], end = g_rp[d + 1];
    float4 acc = make_float4(0.f, 0.f, 0.f, 0.f);
    float denom = 0.f;
    int c8 = j & 7;      // float4 column within 128B row
    int grp = j >> 3;    // edge group 0..3
    for (int base = beg; base < end; base += 32) {
        int idx = base + j;
        int s = 0; float ex = 0.f;
        if (idx < end) {
            float4 r = g_pack[idx];
            s = __float_as_int(r.x);
            float ae = (L == 0) ? r.y : (L == 1) ? r.z : r.w;
            ex = __expf(lrelu(asc[s] + adst_d + ae));
        }
        denom += ex;
        int trips = (min(end - base, 32) + 3) >> 2;
        for (int k = 0; k < trips; k++) {
            int sl = k * 4 + grp;
            float exk = __shfl_sync(0xffffffffu, ex, sl);
            int   sk  = __shfl_sync(0xffffffffu, s, sl);
            float4 hv = hc[sk * 8 + c8];
            acc.x += exk * hv.x; acc.y += exk * hv.y;
            acc.z += exk * hv.z; acc.w += exk * hv.w;
        }
    }
    // reduce the 4 edge-groups (lanes sharing c8)
#pragma unroll
    for (int o = 8; o <= 16; o <<= 1) {
        acc.x += __shfl_xor_sync(0xffffffffu, acc.x, o);
        acc.y += __shfl_xor_sync(0xffffffffu, acc.y, o);
        acc.z += __shfl_xor_sync(0xffffffffu, acc.z, o);
        acc.w += __shfl_xor_sync(0xffffffffu, acc.w, o);
    }
    // redistribute: lane j takes component j&3 from lane j>>2
    int sl2 = j >> 2;
    float v0 = __shfl_sync(0xffffffffu, acc.x, sl2);
    float v1 = __shfl_sync(0xffffffffu, acc.y, sl2);
    float v2 = __shfl_sync(0xffffffffu, acc.z, sl2);
    float v3 = __shfl_sync(0xffffffffu, acc.w, sl2);
    float lo = (j & 1) ? v1 : v0;
    float hi = (j & 1) ? v3 : v2;
    float a  = (j & 2) ? hi : lo;
    denom = wreduce(denom);
    float le = __expf(lrelu(asrc_d + adst_d + aloop));
    float inv = 1.f / (denom + le + 1e-16f);
    float hdj = ((const float*)hc)[d * 32 + j];
    return (a + le * hdj) * inv;
}

// ---------------- 4,5: agg + readout partial + next-layer matmul (register weights) ----
template <int L>
__global__ void __launch_bounds__(256) k_aggF(const float* __restrict__ Wn,
                                              const float* __restrict__ bbc,
                                              const float* __restrict__ asn,
                                              const float* __restrict__ adn,
                                              const float* __restrict__ Wl3, int n) {
    const float4* hc = g_h4[L & 1];
    float4*       hn = g_h4[(L & 1) ^ 1];
    constexpr int P = L & 1;
    int t = threadIdx.x, j = t & 31, w = t >> 5;
    // next-layer weight column j in registers
    float wreg[32];
#pragma unroll
    for (int d2 = 0; d2 < 32; d2++) wreg[d2] = Wn[d2 * 32 + j];
    float bbj = bbc[j], asj = asn[j], adj = adn[j], wlj = Wl3[L * 32 + j];
    float aloop = g_prm[320 + 5 * L + 4];
    int base = (blockIdx.x * 8 + w) * NPW;
#pragma unroll 1
    for (int k = 0; k < NPW; k++) {
        int d = base + k;
        if (d >= n) return;
        float adst_d = g_ad[P][d];
        float asrc_d = g_as[P][d];
        float xl = agg_node<L>(d, j, hc, g_as[P], adst_d, aloop, asrc_d);
        float y = xl + bbj;
        float v = wreduce(y * wlj);
        if (j == 0) {
            if (L == 0) g_vacc[d] = v;
            else        g_vacc[d] += v;
        }
        // h' = y @ Wn via shfl broadcast + register weights
        float h = 0.f;
#pragma unroll
        for (int d2 = 0; d2 < 32; d2++)
            h += __shfl_sync(0xffffffffu, y, d2) * wreg[d2];
        ((float*)hn)[d * 32 + j] = h;
        float sa = wreduce(h * asj);
        float sd = wreduce(h * adj);
        if (j == 0) { g_as[P ^ 1][d] = sa; g_ad[P ^ 1][d] = sd; }
    }
}

// ---------------- 6: layer 2 agg + final readout ----------------
__global__ void __launch_bounds__(256) k_aggL(const int* __restrict__ batch,
                                              const float* __restrict__ Wl3,
                                              const float* __restrict__ bb2, int n) {
    int t = threadIdx.x, j = t & 31, w = t >> 5;
    float wlj = Wl3[64 + j], bbj = bb2[j];
    float aloop = g_prm[320 + 10 + 4];
    int base = (blockIdx.x * 8 + w) * NPW;
#pragma unroll 1
    for (int k = 0; k < NPW; k++) {
        int d = base + k;
        if (d >= n) return;
        float adst_d = g_ad[0][d];
        float asrc_d = g_as[0][d];
        float x3 = agg_node<2>(d, j, g_h4[0], g_as[0], adst_d, aloop, asrc_d);
        float v = wreduce((x3 + bbj) * wlj);
        if (j == 0) {
            int g = batch[d];
            atomicAdd(&g_gsum[g], g_vacc[d] + v);
            atomicAdd(&g_gcnt[g], 1.f);
        }
    }
}

// ---------------- 7: final mean + bias, restore zeros ----------------
__global__ void k_final(float* __restrict__ out, const float* __restrict__ b_l3, int G) {
    int g = blockIdx.x * blockDim.x + threadIdx.x;
    if (g < G) {
        out[g] = g_gsum[g] / fmaxf(g_gcnt[g], 1.f) + b_l3[0];
        g_gsum[g] = 0.f;
        g_gcnt[g] = 0.f;
    }
}

// ---------------- launch ----------------
extern "C" void kernel_launch(void* const* d_in, const int* in_sizes, int n_in,
                              void* d_out, int out_size) {
    const float* nf    = (const float*)d_in[0];
    const int*   ei    = (const int*)d_in[1];
    const float* ea    = (const float*)d_in[2];
    const int*   batch = (const int*)d_in[3];
    const float* W_ne  = (const float*)d_in[4];
    const float* b_ne  = (const float*)d_in[5];
    const float* W_ee  = (const float*)d_in[6];
    const float* b_ee  = (const float*)d_in[7];
    const float* W_l3  = (const float*)d_in[8];
    const float* b_l3  = (const float*)d_in[9];
    const float* W[3]   = {(const float*)d_in[10], (const float*)d_in[16], (const float*)d_in[22]};
    const float* as_[3] = {(const float*)d_in[11], (const float*)d_in[17], (const float*)d_in[23]};
    const float* ad_[3] = {(const float*)d_in[12], (const float*)d_in[18], (const float*)d_in[24]};
    const float* We_[3] = {(const float*)d_in[13], (const float*)d_in[19], (const float*)d_in[25]};
    const float* ae_[3] = {(const float*)d_in[14], (const float*)d_in[20], (const float*)d_in[26]};
    const float* bb_[3] = {(const float*)d_in[15], (const float*)d_in[21], (const float*)d_in[27]};

    int n = in_sizes[3];
    int E = in_sizes[1] / 2;
    int G = out_size;
    const int* src = ei;
    const int* dst = ei + E;

    int eb  = (E + 255) / 256;
    int nb  = (n + 255) / 256;
    int nwb = (n + 8 * NPW - 1) / (8 * NPW);

    k_countB<<<1184, 256>>>(dst, ea, E);
    k_scanprep<<<1, 1024>>>(W_ne, b_ne, W_ee, b_ee, W[0],
                            We_[0], ae_[0], We_[1], ae_[1], We_[2], ae_[2], n, E);
    k_build<<<eb + nb, 256>>>(src, dst, ea, nf, as_[0], ad_[0], E, n, eb);
    k_aggF<0><<<nwb, 256>>>(W[1], bb_[0], as_[1], ad_[1], W_l3, n);
    k_aggF<1><<<nwb, 256>>>(W[2], bb_[1], as_[2], ad_[2], W_l3, n);
    k_aggL<<<nwb, 256>>>(batch, W_l3, bb_[2], n);
    k_final<<<1, 128>>>((float*)d_out, b_l3, G);
}